// round 10
// baseline (speedup 1.0000x reference)
#include <cuda_runtime.h>
#include <cuda_fp16.h>
#include <math.h>
#include <stdint.h>

// Problem constants
#define T_TOK 4096
#define D_IN  768
#define NE    8
#define TOPK  2
#define HID   3072
#define OUTD  768
#define NPAIR (T_TOK * TOPK)   // 8192

// -------------------- device scratch --------------------
__device__ int    g_cnt[NE];          // static-zero; re-zeroed by k_tail each call
__device__ int    g_off[NE + 1];
__device__ int    g_top_i[NPAIR];
__device__ float  g_top_w[NPAIR];
__device__ int    g_pair_token[NPAIR];
__device__ int    g_token_pos[NPAIR];
__device__ __half g_h[(size_t)NPAIR * HID];         // GELU(h) fp16 (~50 MB)
__device__ float  g_y[(size_t)NPAIR * OUTD];        // expert outputs (~25 MB)
__device__ __half g_xh[(size_t)T_TOK * D_IN];       // x fp16
__device__ __half g_w1h[(size_t)NE * HID * D_IN];   // W1^T fp16: [e][H][D]
__device__ __half g_w2h[(size_t)NE * OUTD * HID];   // W2^T fp16: [e][O][H]

// -------------------- helpers --------------------
__device__ __forceinline__ float gelu_exact(float v) {
    return 0.5f * v * (1.0f + erff(v * 0.70710678118654752440f));
}

// -------------------- K0: gate (warp per token) + x -> fp16 --------------------
__global__ void k_gate(const float* __restrict__ x, const float* __restrict__ Wg,
                       float* __restrict__ gate_out) {
    int warp = threadIdx.x >> 5;
    int lane = threadIdx.x & 31;
    int t = blockIdx.x * 8 + warp;
    if (t >= T_TOK) return;
    const float* xr = x + (size_t)t * D_IN;

    float acc[NE];
#pragma unroll
    for (int e = 0; e < NE; e++) acc[e] = 0.f;

    for (int d = lane; d < D_IN; d += 32) {
        float xv = xr[d];
        g_xh[(size_t)t * D_IN + d] = __float2half_rn(xv);
        const float* wr = Wg + d * NE;
#pragma unroll
        for (int e = 0; e < NE; e++) acc[e] += xv * wr[e];
    }
#pragma unroll
    for (int s = 16; s; s >>= 1) {
#pragma unroll
        for (int e = 0; e < NE; e++) acc[e] += __shfl_xor_sync(0xffffffffu, acc[e], s);
    }

    if (lane == 0) {
        // top-2, jax tie-break: lower index first (strict >)
        int i1 = 0; float v1 = acc[0];
#pragma unroll
        for (int e = 1; e < NE; e++) if (acc[e] > v1) { v1 = acc[e]; i1 = e; }
        int i2 = -1; float v2 = -INFINITY;
#pragma unroll
        for (int e = 0; e < NE; e++) {
            if (e == i1) continue;
            if (acc[e] > v2) { v2 = acc[e]; i2 = e; }
        }
        float ex = expf(v2 - v1);
        float inv = 1.f / (1.f + ex);
        float w1 = inv;
        float w2 = ex * inv;

        if (gate_out) {
            float* go = gate_out + (size_t)t * NE;
#pragma unroll
            for (int e = 0; e < NE; e++) go[e] = 0.f;
            go[i1] = w1;
            go[i2] = w2;
        }
        g_top_i[t * 2 + 0] = i1;
        g_top_i[t * 2 + 1] = i2;
        g_top_w[t * 2 + 0] = w1;
        g_top_w[t * 2 + 1] = w2;
        atomicAdd(&g_cnt[i1], 1);
        atomicAdd(&g_cnt[i2], 1);
    }
}

// -------------------- K1: fused prefix + scatter (one block) ------------------
__global__ void k_prefix_scatter() {
    __shared__ int s_fill[NE];
    int tid = threadIdx.x;
    if (tid == 0) {
        int s = 0;
        for (int e = 0; e < NE; e++) {
            g_off[e] = s;
            s_fill[e] = s;
            s += g_cnt[e];
        }
        g_off[NE] = s;
    }
    __syncthreads();
    for (int t = tid; t < T_TOK; t += blockDim.x) {
#pragma unroll
        for (int k = 0; k < TOPK; k++) {
            int e = g_top_i[t * 2 + k];
            int pos = atomicAdd(&s_fill[e], 1);
            g_pair_token[pos] = t;
            g_token_pos[t * 2 + k] = pos;
        }
    }
}

// -------------------- K2: transpose + fp16 convert of W1, W2 ------------------
// W1 [e][D][H] -> g_w1h [e][H][D];  W2 [e][H][O] -> g_w2h [e][O][H]
__global__ void __launch_bounds__(256) k_cvtw(const float* __restrict__ W1,
                                              const float* __restrict__ W2) {
    __shared__ float sm[32][33];
    int bid = blockIdx.x;
    int tx = threadIdx.x & 31, ty = threadIdx.x >> 5;
    bool isW1 = bid < NE * 2304;
    int b = isW1 ? bid : bid - NE * 2304;
    int e = b / 2304, t = b % 2304;
    int R, C, rt, ct;
    const float* src;
    __half* dst;
    if (isW1) { R = D_IN; C = HID;  rt = t / 96; ct = t % 96;
                src = W1 + (size_t)e * R * C; dst = g_w1h + (size_t)e * R * C; }
    else      { R = HID;  C = OUTD; rt = t / 24; ct = t % 24;
                src = W2 + (size_t)e * R * C; dst = g_w2h + (size_t)e * R * C; }
    int r0 = rt * 32, c0 = ct * 32;
#pragma unroll
    for (int j = 0; j < 4; j++)
        sm[ty + 8 * j][tx] = src[(size_t)(r0 + ty + 8 * j) * C + c0 + tx];
    __syncthreads();
#pragma unroll
    for (int j = 0; j < 4; j++)
        dst[(size_t)(c0 + ty + 8 * j) * R + r0 + tx] = __float2half_rn(sm[tx][ty + 8 * j]);
}

// -------------------- pipelined fp16 mma GEMM (ldmatrix fragments) ------------
// Per expert e: Out[p, n] = act( sum_k A[p,k] * WT[n,k] + bias[n] )
// A: [rows][K] fp16 (gathered or contiguous). WT: [N][K] fp16 (k-contiguous).
#define BM 128
#define BN 128
#define BK 32
#define STAGES 4
#define AH 40                     // A smem row stride in halfs (32 + 8 pad)
#define BH 40                     // B smem row stride in halfs
#define A_ENT (BM * AH)           // 5120 halfs
#define B_ENT (BN * BH)           // 5120 halfs
#define STG_ENT (A_ENT + B_ENT)   // 10240 halfs = 20480 B
#define GEMM_SMEM (STAGES * STG_ENT * 2)   // 81920 B

template <int N, int K, bool GATHER>
__global__ void __launch_bounds__(256)
k_gemm(const float* __restrict__ bias) {
    extern __shared__ __half smbuf[];

    const int e = blockIdx.z;
    const int cnt = g_cnt[e];
    const int mBase = blockIdx.y * BM;
    if (mBase >= cnt) return;
    const int off = g_off[e];
    const int n0 = blockIdx.x * BN;

    const float* bp = bias + (size_t)e * N;
    const __half* Ab = GATHER ? g_xh : g_h;
    const __half* Wb = (GATHER ? g_w1h : g_w2h) + (size_t)e * N * K;

    const int tid = threadIdx.x;
    const int lane = tid & 31;
    const int warp = tid >> 5;
    const int wm = warp >> 1;   // 0..3 -> 32 rows each
    const int wn = warp & 1;    // 0..1 -> 64 cols each

    constexpr int KT = K / BK;

    // A-row gather ids for this thread's 2 chunks (constant over k)
    int arow[2];
#pragma unroll
    for (int i = 0; i < 2; i++) {
        int c = tid + i * 256;
        int r = mBase + (c >> 2);
        arow[i] = (r < cnt) ? (GATHER ? g_pair_token[off + r] : off + r) : -1;
    }

    // ---- per-thread ldmatrix base byte-offsets (hoisted out of k-loop) ----
    const uint32_t smbase = (uint32_t)__cvta_generic_to_shared(smbuf);
    uint32_t aoff[2], boff[4];
#pragma unroll
    for (int mt = 0; mt < 2; mt++)
        aoff[mt] = (uint32_t)(((wm * 32 + mt * 16 + (lane & 15)) * AH +
                               (lane >> 4) * 8) * 2);
#pragma unroll
    for (int j = 0; j < 4; j++)
        boff[j] = (uint32_t)(((wn * 64 + j * 16 + (lane >> 4) * 8 + (lane & 7)) * BH +
                              ((lane >> 3) & 1) * 8) * 2 + A_ENT * 2);

    float acc[2][8][4];
#pragma unroll
    for (int mt = 0; mt < 2; mt++)
#pragma unroll
        for (int nt = 0; nt < 8; nt++)
#pragma unroll
            for (int i = 0; i < 4; i++) acc[mt][nt][i] = 0.f;

    auto load_stage = [&](int stage, int kt) {
        __half* As = smbuf + stage * STG_ENT;
        __half* Bs = As + A_ENT;
        int k0 = kt * BK;
        // A tile: 128 rows x 32 halfs = 512 chunks of 16B, 2 per thread
#pragma unroll
        for (int i = 0; i < 2; i++) {
            int c = tid + i * 256;
            int row = c >> 2, q = c & 3;
            int sr = arow[i] >= 0 ? arow[i] : 0;
            const __half* src = Ab + (size_t)sr * K + k0 + q * 8;
            unsigned dst = (unsigned)__cvta_generic_to_shared(As + row * AH + q * 8);
            int sz = arow[i] >= 0 ? 16 : 0;      // zero-fill rows past cnt
            asm volatile("cp.async.cg.shared.global [%0], [%1], 16, %2;\n"
                         :: "r"(dst), "l"(src), "r"(sz));
        }
        // B tile: 128 n-rows x 32 halfs = 512 chunks, 2 per thread
#pragma unroll
        for (int i = 0; i < 2; i++) {
            int c = tid + i * 256;
            int row = c >> 2, q = c & 3;
            const __half* src = Wb + (size_t)(n0 + row) * K + k0 + q * 8;
            unsigned dst = (unsigned)__cvta_generic_to_shared(Bs + row * BH + q * 8);
            asm volatile("cp.async.cg.shared.global [%0], [%1], 16;\n"
                         :: "r"(dst), "l"(src));
        }
    };

    // prologue: prefetch stages 0..STAGES-2
#pragma unroll
    for (int s = 0; s < STAGES - 1; s++) {
        load_stage(s, s);
        asm volatile("cp.async.commit_group;\n");
    }

    for (int kt = 0; kt < KT; kt++) {
        asm volatile("cp.async.wait_group %0;\n" :: "n"(STAGES - 2));
        __syncthreads();

        int kn = kt + STAGES - 1;
        if (kn < KT) load_stage(kn % STAGES, kn);
        asm volatile("cp.async.commit_group;\n");

        const uint32_t stb = smbase + (uint32_t)((kt % STAGES) * STG_ENT * 2);

#pragma unroll
        for (int ks = 0; ks < 2; ks++) {        // 2 k-steps of 16
            const uint32_t kb = (uint32_t)(ks * 32);   // 16 halfs
            uint32_t a[2][4], b[8][2];
#pragma unroll
            for (int mt = 0; mt < 2; mt++) {
                asm volatile("ldmatrix.sync.aligned.m8n8.x4.shared.b16 "
                             "{%0,%1,%2,%3}, [%4];"
                             : "=r"(a[mt][0]), "=r"(a[mt][1]),
                               "=r"(a[mt][2]), "=r"(a[mt][3])
                             : "r"(stb + aoff[mt] + kb));
            }
#pragma unroll
            for (int j = 0; j < 4; j++) {
                asm volatile("ldmatrix.sync.aligned.m8n8.x4.shared.b16 "
                             "{%0,%1,%2,%3}, [%4];"
                             : "=r"(b[2 * j][0]), "=r"(b[2 * j][1]),
                               "=r"(b[2 * j + 1][0]), "=r"(b[2 * j + 1][1])
                             : "r"(stb + boff[j] + kb));
            }
#pragma unroll
            for (int mt = 0; mt < 2; mt++) {
#pragma unroll
                for (int nt = 0; nt < 8; nt++) {
                    asm volatile(
                        "mma.sync.aligned.m16n8k16.row.col.f32.f16.f16.f32 "
                        "{%0,%1,%2,%3}, {%4,%5,%6,%7}, {%8,%9}, {%0,%1,%2,%3};\n"
                        : "+f"(acc[mt][nt][0]), "+f"(acc[mt][nt][1]),
                          "+f"(acc[mt][nt][2]), "+f"(acc[mt][nt][3])
                        : "r"(a[mt][0]), "r"(a[mt][1]), "r"(a[mt][2]), "r"(a[mt][3]),
                          "r"(b[nt][0]), "r"(b[nt][1]));
                }
            }
        }
        __syncthreads();
    }

    // ---- epilogue ----
#pragma unroll
    for (int mt = 0; mt < 2; mt++) {
        int rbase = mBase + wm * 32 + mt * 16 + (lane >> 2);
#pragma unroll
        for (int half = 0; half < 2; half++) {
            int r = rbase + half * 8;
            if (r < cnt) {
                size_t p = (size_t)(off + r);
#pragma unroll
                for (int nt = 0; nt < 8; nt++) {
                    int col = n0 + wn * 64 + nt * 8 + (lane & 3) * 2;
                    float v0 = acc[mt][nt][half * 2 + 0] + bp[col + 0];
                    float v1 = acc[mt][nt][half * 2 + 1] + bp[col + 1];
                    if (GATHER) {   // GEMM1 -> GELU -> fp16
                        __half2 hv = __floats2half2_rn(gelu_exact(v0), gelu_exact(v1));
                        *(__half2*)(g_h + p * N + col) = hv;
                    } else {        // GEMM2 -> float
                        g_y[p * N + col + 0] = v0;
                        g_y[p * N + col + 1] = v1;
                    }
                }
            }
        }
    }
}

// -------------------- K5: weighted combine --------------------
__global__ void k_combine(float* __restrict__ out) {
    int idx = blockIdx.x * blockDim.x + threadIdx.x;
    const int qperrow = OUTD / 4;
    if (idx >= T_TOK * qperrow) return;
    int t = idx / qperrow;
    int q = idx - t * qperrow;

    int p0 = g_token_pos[t * 2 + 0];
    int p1 = g_token_pos[t * 2 + 1];
    float w0 = g_top_w[t * 2 + 0];
    float w1 = g_top_w[t * 2 + 1];

    float4 a = *(const float4*)(g_y + (size_t)p0 * OUTD + q * 4);
    float4 b = *(const float4*)(g_y + (size_t)p1 * OUTD + q * 4);
    float4 o;
    o.x = w0 * a.x + w1 * b.x;
    o.y = w0 * a.y + w1 * b.y;
    o.z = w0 * a.z + w1 * b.z;
    o.w = w0 * a.w + w1 * b.w;
    *(float4*)(out + (size_t)t * OUTD + q * 4) = o;
}

// -------------------- K6: tail — re-zero counters --------------------
__global__ void k_tail() {
    if (threadIdx.x < NE) g_cnt[threadIdx.x] = 0;
}

// -------------------- launch --------------------
extern "C" void kernel_launch(void* const* d_in, const int* in_sizes, int n_in,
                              void* d_out, int out_size) {
    const float* x  = (const float*)d_in[0];
    const float* Wg = (const float*)d_in[1];
    const float* W1 = (const float*)d_in[2];
    const float* b1 = (const float*)d_in[3];
    const float* W2 = (const float*)d_in[4];
    const float* b2 = (const float*)d_in[5];

    float* out = (float*)d_out;
    float* gate = nullptr;
    if ((size_t)out_size >= (size_t)T_TOK * OUTD + (size_t)T_TOK * NE)
        gate = out + (size_t)T_TOK * OUTD;

    cudaFuncSetAttribute(k_gemm<HID, D_IN, true>,
                         cudaFuncAttributeMaxDynamicSharedMemorySize, GEMM_SMEM);
    cudaFuncSetAttribute(k_gemm<OUTD, HID, false>,
                         cudaFuncAttributeMaxDynamicSharedMemorySize, GEMM_SMEM);

    // stream idx: 0 gate, 1 prefix_scatter, 2 cvtw, 3 gemm1 (ncu -s5), 4 gemm2,
    //             5 combine, 6 tail
    k_gate<<<T_TOK / 8, 256>>>(x, Wg, gate);
    k_prefix_scatter<<<1, 256>>>();
    k_cvtw<<<2 * NE * 2304, 256>>>(W1, W2);

    dim3 g1(HID / BN, T_TOK / BM, NE);   // 24 x 32 x 8, most m-tiles exit early
    k_gemm<HID, D_IN, true><<<g1, 256, GEMM_SMEM>>>(b1);

    dim3 g2(OUTD / BN, T_TOK / BM, NE);  // 6 x 32 x 8
    k_gemm<OUTD, HID, false><<<g2, 256, GEMM_SMEM>>>(b2);

    k_combine<<<(T_TOK * (OUTD / 4) + 255) / 256, 256>>>(out);
    k_tail<<<1, 32>>>();
}

// round 11
// speedup vs baseline: 1.2557x; 1.2557x over previous
#include <cuda_runtime.h>
#include <cuda_fp16.h>
#include <math.h>
#include <stdint.h>

// Problem constants
#define T_TOK 4096
#define D_IN  768
#define NE    8
#define TOPK  2
#define HID   3072
#define OUTD  768
#define NPAIR (T_TOK * TOPK)   // 8192

// -------------------- device scratch --------------------
__device__ int    g_cnt[NE];          // static-zero; re-zeroed by k_tail each call
__device__ int    g_off[NE + 1];
__device__ int    g_top_i[NPAIR];
__device__ float  g_top_w[NPAIR];
__device__ int    g_pair_token[NPAIR];
__device__ int    g_token_pos[NPAIR];
__device__ __half g_h[(size_t)NPAIR * HID];         // GELU(h) fp16 (~50 MB)
__device__ float  g_y[(size_t)NPAIR * OUTD];        // expert outputs (~25 MB)
__device__ __half g_xh[(size_t)T_TOK * D_IN];       // x fp16
__device__ __half g_w1h[(size_t)NE * HID * D_IN];   // W1^T fp16: [e][H][D]
__device__ __half g_w2h[(size_t)NE * OUTD * HID];   // W2^T fp16: [e][O][H]

// -------------------- helpers --------------------
__device__ __forceinline__ float gelu_exact(float v) {
    return 0.5f * v * (1.0f + erff(v * 0.70710678118654752440f));
}

// -------------------- K0: gate (warp per token) + x -> fp16 --------------------
__global__ void k_gate(const float* __restrict__ x, const float* __restrict__ Wg,
                       float* __restrict__ gate_out) {
    int warp = threadIdx.x >> 5;
    int lane = threadIdx.x & 31;
    int t = blockIdx.x * 8 + warp;
    if (t >= T_TOK) return;
    const float* xr = x + (size_t)t * D_IN;

    float acc[NE];
#pragma unroll
    for (int e = 0; e < NE; e++) acc[e] = 0.f;

    for (int d = lane; d < D_IN; d += 32) {
        float xv = xr[d];
        g_xh[(size_t)t * D_IN + d] = __float2half_rn(xv);
        const float* wr = Wg + d * NE;
#pragma unroll
        for (int e = 0; e < NE; e++) acc[e] += xv * wr[e];
    }
#pragma unroll
    for (int s = 16; s; s >>= 1) {
#pragma unroll
        for (int e = 0; e < NE; e++) acc[e] += __shfl_xor_sync(0xffffffffu, acc[e], s);
    }

    if (lane == 0) {
        // top-2, jax tie-break: lower index first (strict >)
        int i1 = 0; float v1 = acc[0];
#pragma unroll
        for (int e = 1; e < NE; e++) if (acc[e] > v1) { v1 = acc[e]; i1 = e; }
        int i2 = -1; float v2 = -INFINITY;
#pragma unroll
        for (int e = 0; e < NE; e++) {
            if (e == i1) continue;
            if (acc[e] > v2) { v2 = acc[e]; i2 = e; }
        }
        float ex = expf(v2 - v1);
        float inv = 1.f / (1.f + ex);
        float w1 = inv;
        float w2 = ex * inv;

        if (gate_out) {
            float* go = gate_out + (size_t)t * NE;
#pragma unroll
            for (int e = 0; e < NE; e++) go[e] = 0.f;
            go[i1] = w1;
            go[i2] = w2;
        }
        g_top_i[t * 2 + 0] = i1;
        g_top_i[t * 2 + 1] = i2;
        g_top_w[t * 2 + 0] = w1;
        g_top_w[t * 2 + 1] = w2;
        atomicAdd(&g_cnt[i1], 1);
        atomicAdd(&g_cnt[i2], 1);
    }
}

// -------------------- K1: fused prefix + scatter (one block) ------------------
__global__ void k_prefix_scatter() {
    __shared__ int s_fill[NE];
    int tid = threadIdx.x;
    if (tid == 0) {
        int s = 0;
        for (int e = 0; e < NE; e++) {
            g_off[e] = s;
            s_fill[e] = s;
            s += g_cnt[e];
        }
        g_off[NE] = s;
    }
    __syncthreads();
    for (int t = tid; t < T_TOK; t += blockDim.x) {
#pragma unroll
        for (int k = 0; k < TOPK; k++) {
            int e = g_top_i[t * 2 + k];
            int pos = atomicAdd(&s_fill[e], 1);
            g_pair_token[pos] = t;
            g_token_pos[t * 2 + k] = pos;
        }
    }
}

// -------------------- K2: transpose + fp16 convert of W1, W2 ------------------
// W1 [e][D][H] -> g_w1h [e][H][D];  W2 [e][H][O] -> g_w2h [e][O][H]
__global__ void __launch_bounds__(256) k_cvtw(const float* __restrict__ W1,
                                              const float* __restrict__ W2) {
    __shared__ float sm[32][33];
    int bid = blockIdx.x;
    int tx = threadIdx.x & 31, ty = threadIdx.x >> 5;
    bool isW1 = bid < NE * 2304;
    int b = isW1 ? bid : bid - NE * 2304;
    int e = b / 2304, t = b % 2304;
    int R, C, rt, ct;
    const float* src;
    __half* dst;
    if (isW1) { R = D_IN; C = HID;  rt = t / 96; ct = t % 96;
                src = W1 + (size_t)e * R * C; dst = g_w1h + (size_t)e * R * C; }
    else      { R = HID;  C = OUTD; rt = t / 24; ct = t % 24;
                src = W2 + (size_t)e * R * C; dst = g_w2h + (size_t)e * R * C; }
    int r0 = rt * 32, c0 = ct * 32;
#pragma unroll
    for (int j = 0; j < 4; j++)
        sm[ty + 8 * j][tx] = src[(size_t)(r0 + ty + 8 * j) * C + c0 + tx];
    __syncthreads();
#pragma unroll
    for (int j = 0; j < 4; j++)
        dst[(size_t)(c0 + ty + 8 * j) * R + r0 + tx] = __float2half_rn(sm[tx][ty + 8 * j]);
}

// -------------------- pipelined fp16 mma GEMM (BK=64, ldmatrix) ---------------
// Per expert e: Out[p, n] = act( sum_k A[p,k] * WT[n,k] + bias[n] )
// A: [rows][K] fp16 (gathered or contiguous). WT: [N][K] fp16 (k-contiguous).
#define BM 128
#define BN 128
#define BK 64
#define STAGES 3
#define AH 72                     // A smem row stride in halfs (64 + 8 pad)
#define BH 72                     // B smem row stride in halfs
#define A_ENT (BM * AH)           // 9216 halfs
#define B_ENT (BN * BH)           // 9216 halfs
#define STG_ENT (A_ENT + B_ENT)   // 18432 halfs = 36864 B
#define GEMM_SMEM (STAGES * STG_ENT * 2)   // 110592 B

template <int N, int K, bool GATHER>
__global__ void __launch_bounds__(256)
k_gemm(const float* __restrict__ bias) {
    extern __shared__ __half smbuf[];

    const int e = blockIdx.z;
    const int cnt = g_cnt[e];
    const int mBase = blockIdx.y * BM;
    if (mBase >= cnt) return;
    const int off = g_off[e];
    const int n0 = blockIdx.x * BN;

    const float* bp = bias + (size_t)e * N;
    const __half* Ab = GATHER ? g_xh : g_h;
    const __half* Wb = (GATHER ? g_w1h : g_w2h) + (size_t)e * N * K;

    const int tid = threadIdx.x;
    const int lane = tid & 31;
    const int warp = tid >> 5;
    const int wm = warp >> 1;   // 0..3 -> 32 rows each
    const int wn = warp & 1;    // 0..1 -> 64 cols each

    constexpr int KT = K / BK;  // 12 (gemm1) / 48 (gemm2)

    // A-row gather ids for this thread's 4 chunks (constant over k)
    int arow[4];
#pragma unroll
    for (int i = 0; i < 4; i++) {
        int c = tid + i * 256;
        int r = mBase + (c >> 3);
        arow[i] = (r < cnt) ? (GATHER ? g_pair_token[off + r] : off + r) : -1;
    }

    // ---- per-thread ldmatrix base byte-offsets (hoisted out of k-loop) ----
    const uint32_t smbase = (uint32_t)__cvta_generic_to_shared(smbuf);
    uint32_t aoff[2], boff[4];
#pragma unroll
    for (int mt = 0; mt < 2; mt++)
        aoff[mt] = (uint32_t)(((wm * 32 + mt * 16 + (lane & 15)) * AH +
                               (lane >> 4) * 8) * 2);
#pragma unroll
    for (int j = 0; j < 4; j++)
        boff[j] = (uint32_t)(((wn * 64 + j * 16 + (lane >> 4) * 8 + (lane & 7)) * BH +
                              ((lane >> 3) & 1) * 8) * 2 + A_ENT * 2);

    float acc[2][8][4];
#pragma unroll
    for (int mt = 0; mt < 2; mt++)
#pragma unroll
        for (int nt = 0; nt < 8; nt++)
#pragma unroll
            for (int i = 0; i < 4; i++) acc[mt][nt][i] = 0.f;

    auto load_stage = [&](int stage, int kt) {
        __half* As = smbuf + stage * STG_ENT;
        __half* Bs = As + A_ENT;
        int k0 = kt * BK;
        // A tile: 128 rows x 64 halfs = 1024 chunks of 16B, 4 per thread
#pragma unroll
        for (int i = 0; i < 4; i++) {
            int c = tid + i * 256;
            int row = c >> 3, q = c & 7;
            int sr = arow[i] >= 0 ? arow[i] : 0;
            const __half* src = Ab + (size_t)sr * K + k0 + q * 8;
            unsigned dst = (unsigned)__cvta_generic_to_shared(As + row * AH + q * 8);
            int sz = arow[i] >= 0 ? 16 : 0;      // zero-fill rows past cnt
            asm volatile("cp.async.cg.shared.global [%0], [%1], 16, %2;\n"
                         :: "r"(dst), "l"(src), "r"(sz));
        }
        // B tile: 128 n-rows x 64 halfs = 1024 chunks, 4 per thread
#pragma unroll
        for (int i = 0; i < 4; i++) {
            int c = tid + i * 256;
            int row = c >> 3, q = c & 7;
            const __half* src = Wb + (size_t)(n0 + row) * K + k0 + q * 8;
            unsigned dst = (unsigned)__cvta_generic_to_shared(Bs + row * BH + q * 8);
            asm volatile("cp.async.cg.shared.global [%0], [%1], 16;\n"
                         :: "r"(dst), "l"(src));
        }
    };

    // prologue: prefetch stages 0..STAGES-2
#pragma unroll
    for (int s = 0; s < STAGES - 1; s++) {
        load_stage(s, s);
        asm volatile("cp.async.commit_group;\n");
    }

    for (int kt = 0; kt < KT; kt++) {
        asm volatile("cp.async.wait_group %0;\n" :: "n"(STAGES - 2));
        __syncthreads();

        int kn = kt + STAGES - 1;
        if (kn < KT) load_stage(kn % STAGES, kn);
        asm volatile("cp.async.commit_group;\n");

        const uint32_t stb = smbase + (uint32_t)((kt % STAGES) * STG_ENT * 2);

#pragma unroll
        for (int ks = 0; ks < 4; ks++) {        // 4 k-steps of 16
            const uint32_t kb = (uint32_t)(ks * 32);   // 16 halfs
            uint32_t a[2][4], b[8][2];
#pragma unroll
            for (int mt = 0; mt < 2; mt++) {
                asm volatile("ldmatrix.sync.aligned.m8n8.x4.shared.b16 "
                             "{%0,%1,%2,%3}, [%4];"
                             : "=r"(a[mt][0]), "=r"(a[mt][1]),
                               "=r"(a[mt][2]), "=r"(a[mt][3])
                             : "r"(stb + aoff[mt] + kb));
            }
#pragma unroll
            for (int j = 0; j < 4; j++) {
                asm volatile("ldmatrix.sync.aligned.m8n8.x4.shared.b16 "
                             "{%0,%1,%2,%3}, [%4];"
                             : "=r"(b[2 * j][0]), "=r"(b[2 * j][1]),
                               "=r"(b[2 * j + 1][0]), "=r"(b[2 * j + 1][1])
                             : "r"(stb + boff[j] + kb));
            }
#pragma unroll
            for (int mt = 0; mt < 2; mt++) {
#pragma unroll
                for (int nt = 0; nt < 8; nt++) {
                    asm volatile(
                        "mma.sync.aligned.m16n8k16.row.col.f32.f16.f16.f32 "
                        "{%0,%1,%2,%3}, {%4,%5,%6,%7}, {%8,%9}, {%0,%1,%2,%3};\n"
                        : "+f"(acc[mt][nt][0]), "+f"(acc[mt][nt][1]),
                          "+f"(acc[mt][nt][2]), "+f"(acc[mt][nt][3])
                        : "r"(a[mt][0]), "r"(a[mt][1]), "r"(a[mt][2]), "r"(a[mt][3]),
                          "r"(b[nt][0]), "r"(b[nt][1]));
                }
            }
        }
    }

    // ---- epilogue ----
#pragma unroll
    for (int mt = 0; mt < 2; mt++) {
        int rbase = mBase + wm * 32 + mt * 16 + (lane >> 2);
#pragma unroll
        for (int half = 0; half < 2; half++) {
            int r = rbase + half * 8;
            if (r < cnt) {
                size_t p = (size_t)(off + r);
#pragma unroll
                for (int nt = 0; nt < 8; nt++) {
                    int col = n0 + wn * 64 + nt * 8 + (lane & 3) * 2;
                    float v0 = acc[mt][nt][half * 2 + 0] + bp[col + 0];
                    float v1 = acc[mt][nt][half * 2 + 1] + bp[col + 1];
                    if (GATHER) {   // GEMM1 -> GELU -> fp16
                        __half2 hv = __floats2half2_rn(gelu_exact(v0), gelu_exact(v1));
                        *(__half2*)(g_h + p * N + col) = hv;
                    } else {        // GEMM2 -> float
                        g_y[p * N + col + 0] = v0;
                        g_y[p * N + col + 1] = v1;
                    }
                }
            }
        }
    }
}

// -------------------- K5: weighted combine --------------------
__global__ void k_combine(float* __restrict__ out) {
    int idx = blockIdx.x * blockDim.x + threadIdx.x;
    const int qperrow = OUTD / 4;
    if (idx >= T_TOK * qperrow) return;
    int t = idx / qperrow;
    int q = idx - t * qperrow;

    int p0 = g_token_pos[t * 2 + 0];
    int p1 = g_token_pos[t * 2 + 1];
    float w0 = g_top_w[t * 2 + 0];
    float w1 = g_top_w[t * 2 + 1];

    float4 a = *(const float4*)(g_y + (size_t)p0 * OUTD + q * 4);
    float4 b = *(const float4*)(g_y + (size_t)p1 * OUTD + q * 4);
    float4 o;
    o.x = w0 * a.x + w1 * b.x;
    o.y = w0 * a.y + w1 * b.y;
    o.z = w0 * a.z + w1 * b.z;
    o.w = w0 * a.w + w1 * b.w;
    *(float4*)(out + (size_t)t * OUTD + q * 4) = o;
}

// -------------------- K6: tail — re-zero counters --------------------
__global__ void k_tail() {
    if (threadIdx.x < NE) g_cnt[threadIdx.x] = 0;
}

// -------------------- launch --------------------
extern "C" void kernel_launch(void* const* d_in, const int* in_sizes, int n_in,
                              void* d_out, int out_size) {
    const float* x  = (const float*)d_in[0];
    const float* Wg = (const float*)d_in[1];
    const float* W1 = (const float*)d_in[2];
    const float* b1 = (const float*)d_in[3];
    const float* W2 = (const float*)d_in[4];
    const float* b2 = (const float*)d_in[5];

    float* out = (float*)d_out;
    float* gate = nullptr;
    if ((size_t)out_size >= (size_t)T_TOK * OUTD + (size_t)T_TOK * NE)
        gate = out + (size_t)T_TOK * OUTD;

    cudaFuncSetAttribute(k_gemm<HID, D_IN, true>,
                         cudaFuncAttributeMaxDynamicSharedMemorySize, GEMM_SMEM);
    cudaFuncSetAttribute(k_gemm<OUTD, HID, false>,
                         cudaFuncAttributeMaxDynamicSharedMemorySize, GEMM_SMEM);

    // stream idx: 0 gate, 1 prefix_scatter, 2 cvtw, 3 gemm1 (ncu -s5), 4 gemm2,
    //             5 combine, 6 tail
    k_gate<<<T_TOK / 8, 256>>>(x, Wg, gate);
    k_prefix_scatter<<<1, 256>>>();
    k_cvtw<<<2 * NE * 2304, 256>>>(W1, W2);

    dim3 g1(HID / BN, T_TOK / BM, NE);   // 24 x 32 x 8, most m-tiles exit early
    k_gemm<HID, D_IN, true><<<g1, 256, GEMM_SMEM>>>(b1);

    dim3 g2(OUTD / BN, T_TOK / BM, NE);  // 6 x 32 x 8
    k_gemm<OUTD, HID, false><<<g2, 256, GEMM_SMEM>>>(b2);

    k_combine<<<(T_TOK * (OUTD / 4) + 255) / 256, 256>>>(out);
    k_tail<<<1, 32>>>();
}